// round 16
// baseline (speedup 1.0000x reference)
#include <cuda_runtime.h>
#include <math.h>

#define NL 51
#define NC 16
#define PCX 33          // 16 sums + 16 normsums + count
#define NRED (NL * PCX) // 1683
#define GRID1 296       // 2 CTAs/SM * 148
#define BLK1 512
#define TILE 512
#define NT 8192         // 4194304 voxels / 512
#define ROWB 2064       // staged p row stride (bytes): 512*4 + 16
#define CAP 32

static const long long CH_STRIDE = 1LL << 21;   // floats per channel plane

// dynamic smem layout (bytes)
#define P_OFF(b)    ((b) * 33024)                // 2 bufs, 16 rows * 2064
#define IDX_OFF(b)  (66048 + (b) * 3264)         // 2 bufs ushort[51][32]
#define BINV_OFF(b) (72576 + (b) * 6528)         // 2 bufs float[51][32]
#define CUR_OFF(b)  (85632 + (b) * 208)          // 2 bufs int[51]+pad
#define SS_OFF      86048                        // float[51][16]
#define SN_OFF      89312                        // float[51][16]
#define SCNT_OFF    92576                        // float[51]
#define SMEM1       92800

#define CP_ASYNC16(dst, src) \
    asm volatile("cp.async.cg.shared.global [%0], [%1], 16;\n" :: "r"(dst), "l"(src))
#define CP_COMMIT() asm volatile("cp.async.commit_group;\n" ::: "memory")
#define CP_WAIT1()  asm volatile("cp.async.wait_group 1;\n" ::: "memory")
#define CP_WAIT0()  asm volatile("cp.async.wait_group 0;\n" ::: "memory")

// Global scratch (allocation-free rule). Zero-init at load; restored each call.
static __device__ float g_red_f[NRED];
static __device__ int   g_done;

__device__ __forceinline__ double blockReduceD(double v) {
    __shared__ double sh[32];
    int lane = threadIdx.x & 31, w = threadIdx.x >> 5;
    #pragma unroll
    for (int o = 16; o; o >>= 1) v += __shfl_down_sync(0xffffffffu, v, o);
    if (lane == 0) sh[w] = v;
    __syncthreads();
    int nw = (blockDim.x + 31) >> 5;
    v = (threadIdx.x < nw) ? sh[threadIdx.x] : 0.0;
    if (w == 0) {
        #pragma unroll
        for (int o = 16; o; o >>= 1) v += __shfl_down_sync(0xffffffffu, v, o);
    }
    return v; // valid on thread 0
}

__device__ __forceinline__ void issue_tile(unsigned sm32, int t, int buf,
                                           const float* __restrict__ pred) {
    size_t v0 = (size_t)t * TILE;
    const char* psrc = (const char*)(pred + (v0 >> 21) * (NC * (size_t)CH_STRIDE)
                                          + (v0 & (size_t)(CH_STRIDE - 1)));
    int tid = threadIdx.x;
    #pragma unroll
    for (int it = 0; it < 4; it++) {
        int o = tid + it * BLK1;         // 0..2047
        int k = o >> 7, c = o & 127;
        unsigned dst = sm32 + P_OFF(buf) + k * ROWB + c * 16;
        const char* src = psrc + (size_t)k * ((size_t)CH_STRIDE * 4) + (size_t)c * 16;
        CP_ASYNC16(dst, src);
    }
}

// scatter via LDG: norm + label from global (L2/MSHR hits; tile cp.async in flight)
__device__ __forceinline__ void scatter_ldg(const float* __restrict__ pred,
                                            const int* __restrict__ gt,
                                            int t, int bb, char* sm,
                                            float* sS, float* sN, int tid) {
    size_t v0 = (size_t)t * TILE;
    int l = gt[v0 + tid];
    const float* pb = pred + (v0 >> 21) * (NC * (size_t)CH_STRIDE)
                           + (v0 & (size_t)(CH_STRIDE - 1)) + tid;
    float p[NC];
    #pragma unroll
    for (int kk = 0; kk < NC; kk++) p[kk] = pb[(size_t)kk * CH_STRIDE];
    float q = 0.f;
    #pragma unroll
    for (int kk = 0; kk < NC; kk++) q += p[kk] * p[kk];
    float inv = rsqrtf(fmaxf(q, 1e-30f));

    int* cursor = (int*)(sm + CUR_OFF(bb));
    int r = atomicAdd(&cursor[l], 1);
    if (r < CAP) {
        ((unsigned short*)(sm + IDX_OFF(bb)))[l * CAP + r] = (unsigned short)tid;
        ((float*)(sm + BINV_OFF(bb)))[l * CAP + r] = inv;
    } else {
        #pragma unroll
        for (int kk = 0; kk < NC; kk++) {
            atomicAdd(&sS[l * NC + kk], p[kk]);
            atomicAdd(&sN[l * NC + kk], p[kk] * inv);
        }
    }
}

// gather (R9 form): warp w owns labels l%16==w; ushort4/ILP-4; clears cursor
__device__ __forceinline__ void gather_tile(char* sm, int bp, int bb,
                                            int lane, int w, int k, int s,
                                            float* sS, float* sN, float* scnt) {
    int* cursor = (int*)(sm + CUR_OFF(bb));
    const unsigned short* sidx = (const unsigned short*)(sm + IDX_OFF(bb));
    const float* sbinv = (const float*)(sm + BINV_OFF(bb));
    const char* pbase = sm + P_OFF(bp) + k * ROWB;
    for (int l2 = w; l2 < NL; l2 += 16) {
        int c = cursor[l2];
        int cc = c < CAP ? c : CAP;
        float ar = 0.f, an = 0.f;
        #pragma unroll
        for (int jj = 0; jj < 4; jj++) {
            int i0 = s * 4 + jj * 8;
            if (i0 < cc) {
                ushort4 v4 = *(const ushort4*)&sidx[l2 * CAP + i0];
                float4 n4 = *(const float4*)&sbinv[l2 * CAP + i0];
                float p0 = *(const float*)(pbase + (int)v4.x * 4);
                ar += p0; an += p0 * n4.x;
                if (i0 + 1 < cc) {
                    float p1 = *(const float*)(pbase + (int)v4.y * 4);
                    ar += p1; an += p1 * n4.y;
                }
                if (i0 + 2 < cc) {
                    float p2 = *(const float*)(pbase + (int)v4.z * 4);
                    ar += p2; an += p2 * n4.z;
                }
                if (i0 + 3 < cc) {
                    float p3 = *(const float*)(pbase + (int)v4.w * 4);
                    ar += p3; an += p3 * n4.w;
                }
            }
        }
        ar += __shfl_xor_sync(0xffffffffu, ar, 16);
        an += __shfl_xor_sync(0xffffffffu, an, 16);
        if (s == 0) {
            sS[l2 * NC + k] += ar;
            sN[l2 * NC + k] += an;
        }
        if (lane == 0) { scnt[l2] += (float)c; cursor[l2] = 0; }
    }
}

__global__ void __launch_bounds__(BLK1, 2) k_fused(const float* __restrict__ pred,
                                                   const int* __restrict__ gt,
                                                   float* __restrict__ out) {
    extern __shared__ char sm[];
    float* sS = (float*)(sm + SS_OFF);
    float* sN = (float*)(sm + SN_OFF);
    float* scnt = (float*)(sm + SCNT_OFF);
    const int tid = threadIdx.x;
    const int lane = tid & 31, w = tid >> 5;
    const int k = lane & 15, s = lane >> 4;

    unsigned sm32;
    asm("{ .reg .u64 t; cvta.to.shared.u64 t, %1; cvt.u32.u64 %0, t; }"
        : "=r"(sm32) : "l"(sm));

    for (int i = tid; i < NL * NC; i += BLK1) { sS[i] = 0.f; sN[i] = 0.f; }
    if (tid < NL) {
        scnt[tid] = 0.f;
        ((int*)(sm + CUR_OFF(0)))[tid] = 0;
        ((int*)(sm + CUR_OFF(1)))[tid] = 0;
    }
    __syncthreads();

    const int t0 = blockIdx.x;
    // prologue: stage tiles 0 and 1; scatter tile 0 (LDG-based, independent)
    issue_tile(sm32, t0, 0, pred);
    CP_COMMIT();
    if (t0 + GRID1 < NT) issue_tile(sm32, t0 + GRID1, 1, pred);
    CP_COMMIT();
    CP_WAIT1();          // p[0] staged
    scatter_ldg(pred, gt, t0, 0, sm, sS, sN, tid);

    // mainloop: 2 barriers per tile; scatter(j+1) overlaps gather(j)
    for (int j = 0; t0 + j * GRID1 < NT; j++) {
        int ts = t0 + (j + 1) * GRID1;
        // B1: bins[j&1] complete (scatter j done), p[j&1] staged+waited,
        //     cursor[(j+1)&1] cleared by gather(j-1)
        __syncthreads();
        if (ts < NT) scatter_ldg(pred, gt, ts, (j + 1) & 1, sm, sS, sN, tid);
        gather_tile(sm, j & 1, j & 1, lane, w, k, s, sS, sN, scnt);
        // B2: all threads done reading p[j&1] -> safe to overwrite
        __syncthreads();
        int tn = t0 + (j + 2) * GRID1;
        if (tn < NT) {
            issue_tile(sm32, tn, j & 1, pred);
            CP_COMMIT();
            CP_WAIT1();  // p[j+1] complete before next B1
        } else {
            CP_WAIT0();
        }
    }

    // epilogue: f32 atomic reduce into g_red_f (staggered addresses)
    for (int jj = tid; jj < NRED; jj += BLK1) {
        int i = (jj + blockIdx.x * 53) % NRED;
        int l = i / PCX, v = i % PCX;
        float r;
        if (v < NC) r = sS[l * NC + v];
        else if (v < 2 * NC) r = sN[l * NC + (v - NC)];
        else r = scnt[l];
        atomicAdd(&g_red_f[i], r);
    }

    // last-CTA inline finish
    __shared__ int s_ticket;
    __threadfence();
    __syncthreads();
    if (tid == 0) s_ticket = atomicAdd(&g_done, 1);
    __syncthreads();
    if (s_ticket != GRID1 - 1) return;
    __threadfence();

    float* s_red = (float*)(sm);                 // NRED floats
    float* s_cmn2 = (float*)(sm + 8192);         // (NL-1)*NC floats
    for (int i = tid; i < NRED; i += BLK1) {
        s_red[i] = g_red_f[i];
        g_red_f[i] = 0.f;                        // restore for next graph replay
    }
    if (tid == 0) g_done = 0;
    __syncthreads();

    double intra_c = 0.0;
    if (tid < NL) {
        float cf = fmaxf(s_red[tid * PCX + 32], 1.f);
        float m[NC];
        float n2 = 0.f;
        #pragma unroll
        for (int kk = 0; kk < NC; kk++) {
            m[kk] = s_red[tid * PCX + kk] / cf;
            n2 += m[kk] * m[kk];
        }
        float mn = sqrtf(n2);
        if (tid >= 1) {
            float inv = 1.f / fmaxf(mn, 1e-8f);
            float dot = 0.f;
            #pragma unroll
            for (int kk = 0; kk < NC; kk++) {
                s_cmn2[(tid - 1) * NC + kk] = m[kk] * inv;
                dot += m[kk] * s_red[tid * PCX + NC + kk];
            }
            intra_c = (double)dot / ((double)fmaxf(mn, 1e-30f) * (double)cf);
        }
    }
    __syncthreads();
    double intra = blockReduceD(intra_c);
    __syncthreads();

    double acc = 0.0;
    for (int p = tid; p < 1225; p += BLK1) {
        int i = 0, rem = p;
        while (rem >= (NL - 2) - i) { rem -= (NL - 2) - i; i++; }
        int jx = i + 1 + rem;
        float d = 0.f;
        #pragma unroll
        for (int kk = 0; kk < NC; kk++) d += s_cmn2[i * NC + kk] * s_cmn2[jx * NC + kk];
        d = fminf(fmaxf(d, 0.f), 1.f);
        acc += (double)d;
    }
    __syncthreads();
    double inter = blockReduceD(acc);
    if (tid == 0) out[0] = (float)(inter / 1225.0 - intra / (double)(NL - 1));
}

extern "C" void kernel_launch(void* const* d_in, const int* in_sizes, int n_in,
                              void* d_out, int out_size) {
    const float* pred = (const float*)d_in[0];
    const int* gt = (const int*)d_in[1];
    float* out = (float*)d_out;

    cudaFuncSetAttribute(k_fused, cudaFuncAttributeMaxDynamicSharedMemorySize, SMEM1);
    k_fused<<<GRID1, BLK1, SMEM1>>>(pred, gt, out);
}

// round 17
// speedup vs baseline: 1.0640x; 1.0640x over previous
#include <cuda_runtime.h>
#include <math.h>

#define NL 51
#define NC 16
#define PCX 33          // 16 sums + 16 normsums + count
#define NRED (NL * PCX) // 1683
#define GRID1 296       // 2 CTAs/SM * 148
#define BLK1 640        // 20 warps
#define NW1 20
#define TILE 512
#define NT 8192         // 4194304 voxels / 512
#define ROWB 2064       // staged p row stride (bytes): 512*4 + 16
#define CAP 32

static const long long CH_STRIDE = 1LL << 21;   // floats per channel plane

// dynamic smem layout (bytes) — R9 layout
#define P_OFF(b)   ((b) * 33024)                 // 16 rows * 2064
#define GT_OFF(b)  (66048 + (b) * 2048)
#define IDX_OFF    70144                         // ushort[51][32]
#define BINV_OFF   73408                         // float[51][32]
#define CUR_OFF    79936                         // int[51] + pad
#define SS_OFF     80144                         // float[51][16]
#define SN_OFF     83408                         // float[51][16]
#define SCNT_OFF   86672                         // float[51]
#define SMEM1      86912

#define CP_ASYNC16(dst, src) \
    asm volatile("cp.async.cg.shared.global [%0], [%1], 16;\n" :: "r"(dst), "l"(src))
#define CP_COMMIT() asm volatile("cp.async.commit_group;\n" ::: "memory")
#define CP_WAIT1()  asm volatile("cp.async.wait_group 1;\n" ::: "memory")
#define CP_WAIT0()  asm volatile("cp.async.wait_group 0;\n" ::: "memory")

// Global scratch (allocation-free rule). Zero-init at load; restored each call.
static __device__ float g_red_f[NRED];
static __device__ int   g_done;

__device__ __forceinline__ double blockReduceD(double v) {
    __shared__ double sh[32];
    int lane = threadIdx.x & 31, w = threadIdx.x >> 5;
    #pragma unroll
    for (int o = 16; o; o >>= 1) v += __shfl_down_sync(0xffffffffu, v, o);
    if (lane == 0) sh[w] = v;
    __syncthreads();
    int nw = (blockDim.x + 31) >> 5;
    v = (threadIdx.x < nw) ? sh[threadIdx.x] : 0.0;
    if (w == 0) {
        #pragma unroll
        for (int o = 16; o; o >>= 1) v += __shfl_down_sync(0xffffffffu, v, o);
    }
    return v; // valid on thread 0
}

__device__ __forceinline__ void issue_tile(unsigned sm32, int t, int buf,
                                           const float* __restrict__ pred,
                                           const int* __restrict__ gt) {
    size_t v0 = (size_t)t * TILE;
    const char* psrc = (const char*)(pred + (v0 >> 21) * (NC * (size_t)CH_STRIDE)
                                          + (v0 & (size_t)(CH_STRIDE - 1)));
    int tid = threadIdx.x;
    #pragma unroll
    for (int it = 0; it < 4; it++) {
        int o = tid + it * BLK1;         // 0..2559, need 0..2047
        if (o < 2048) {
            int k = o >> 7, c = o & 127; // 128 16B-granules per 512-float row
            unsigned dst = sm32 + P_OFF(buf) + k * ROWB + c * 16;
            const char* src = psrc + (size_t)k * ((size_t)CH_STRIDE * 4) + (size_t)c * 16;
            CP_ASYNC16(dst, src);
        }
    }
    if (tid < 128) {
        unsigned dstg = sm32 + GT_OFF(buf) + tid * 16;
        const char* srcg = (const char*)(gt + v0) + (size_t)tid * 16;
        CP_ASYNC16(dstg, srcg);
    }
}

// ---------- Fused pass (R9 interior @ 640 threads) + inline finish (R11 tail) ----------
__global__ void __launch_bounds__(BLK1, 2) k_fused(const float* __restrict__ pred,
                                                   const int* __restrict__ gt,
                                                   float* __restrict__ out) {
    extern __shared__ char sm[];
    float* sS = (float*)(sm + SS_OFF);
    float* sN = (float*)(sm + SN_OFF);
    float* scnt = (float*)(sm + SCNT_OFF);
    int* cursor = (int*)(sm + CUR_OFF);
    unsigned short* sidx = (unsigned short*)(sm + IDX_OFF);
    float* sbinv = (float*)(sm + BINV_OFF);
    const int tid = threadIdx.x;
    const int lane = tid & 31, w = tid >> 5;
    const int k = lane & 15, s = lane >> 4;

    unsigned sm32;
    asm("{ .reg .u64 t; cvta.to.shared.u64 t, %1; cvt.u32.u64 %0, t; }"
        : "=r"(sm32) : "l"(sm));

    for (int i = tid; i < NL * NC; i += BLK1) { sS[i] = 0.f; sN[i] = 0.f; }
    if (tid < NL) scnt[tid] = 0.f;
    __syncthreads();

    issue_tile(sm32, blockIdx.x, 0, pred, gt);
    CP_COMMIT();

    int it = 0;
    for (int t = blockIdx.x; t < NT; t += GRID1, it++) {
        int buf = it & 1;
        int tn = t + GRID1;
        if (tn < NT) {
            issue_tile(sm32, tn, buf ^ 1, pred, gt);
            CP_COMMIT();
            CP_WAIT1();
        } else {
            CP_WAIT0();
        }
        __syncthreads();

        if (tid < NL) cursor[tid] = 0;
        __syncthreads();

        // scatter + norm: threads 0..511, 1 voxel/thread; inv-norm in registers
        if (tid < TILE) {
            int l = *(const int*)(sm + GT_OFF(buf) + tid * 4);
            const char* pb = sm + P_OFF(buf) + tid * 4;
            float q = 0.f;
            #pragma unroll
            for (int kk = 0; kk < NC; kk++) {
                float pp = *(const float*)(pb + kk * ROWB);
                q += pp * pp;
            }
            float inv = rsqrtf(fmaxf(q, 1e-30f));
            int r = atomicAdd(&cursor[l], 1);
            if (r < CAP) {
                sidx[l * CAP + r] = (unsigned short)tid;
                sbinv[l * CAP + r] = inv;
            } else {
                #pragma unroll
                for (int kk = 0; kk < NC; kk++) {
                    float pv = *(const float*)(sm + P_OFF(buf) + kk * ROWB + tid * 4);
                    atomicAdd(&sS[l * NC + kk], pv);
                    atomicAdd(&sN[l * NC + kk], pv * inv);
                }
            }
        }
        __syncthreads();

        // gather: warp w owns labels l % 20 == w; dual accumulation, ILP-4
        const char* pbase = sm + P_OFF(buf) + k * ROWB;
        for (int l2 = w; l2 < NL; l2 += NW1) {
            int c = cursor[l2];
            int cc = c < CAP ? c : CAP;
            float ar = 0.f, an = 0.f;
            #pragma unroll
            for (int jj = 0; jj < 4; jj++) {
                int i0 = s * 4 + jj * 8;
                if (i0 < cc) {
                    ushort4 v4 = *(const ushort4*)&sidx[l2 * CAP + i0];
                    float4 n4 = *(const float4*)&sbinv[l2 * CAP + i0];
                    float p0 = *(const float*)(pbase + (int)v4.x * 4);
                    ar += p0; an += p0 * n4.x;
                    if (i0 + 1 < cc) {
                        float p1 = *(const float*)(pbase + (int)v4.y * 4);
                        ar += p1; an += p1 * n4.y;
                    }
                    if (i0 + 2 < cc) {
                        float p2 = *(const float*)(pbase + (int)v4.z * 4);
                        ar += p2; an += p2 * n4.z;
                    }
                    if (i0 + 3 < cc) {
                        float p3 = *(const float*)(pbase + (int)v4.w * 4);
                        ar += p3; an += p3 * n4.w;
                    }
                }
            }
            ar += __shfl_xor_sync(0xffffffffu, ar, 16);
            an += __shfl_xor_sync(0xffffffffu, an, 16);
            if (s == 0) {
                sS[l2 * NC + k] += ar;
                sN[l2 * NC + k] += an;
            }
            if (lane == 0) scnt[l2] += (float)c;
        }
        __syncthreads();   // protect buffer + cursor reuse
    }

    // epilogue: f32 atomic reduce into g_red_f (staggered addresses)
    for (int jj = tid; jj < NRED; jj += BLK1) {
        int i = (jj + blockIdx.x * 53) % NRED;
        int l = i / PCX, v = i % PCX;
        float r;
        if (v < NC) r = sS[l * NC + v];
        else if (v < 2 * NC) r = sN[l * NC + (v - NC)];
        else r = scnt[l];
        atomicAdd(&g_red_f[i], r);
    }

    // last-CTA inline finish
    __shared__ int s_ticket;
    __threadfence();
    __syncthreads();
    if (tid == 0) s_ticket = atomicAdd(&g_done, 1);
    __syncthreads();
    if (s_ticket != GRID1 - 1) return;
    __threadfence();

    float* s_red = (float*)(sm);                 // NRED floats
    float* s_cmn2 = (float*)(sm + 8192);         // (NL-1)*NC floats
    for (int i = tid; i < NRED; i += BLK1) {
        s_red[i] = g_red_f[i];
        g_red_f[i] = 0.f;                        // restore for next graph replay
    }
    if (tid == 0) g_done = 0;
    __syncthreads();

    double intra_c = 0.0;
    if (tid < NL) {
        float cf = fmaxf(s_red[tid * PCX + 32], 1.f);
        float m[NC];
        float n2 = 0.f;
        #pragma unroll
        for (int kk = 0; kk < NC; kk++) {
            m[kk] = s_red[tid * PCX + kk] / cf;
            n2 += m[kk] * m[kk];
        }
        float mn = sqrtf(n2);
        if (tid >= 1) {
            float inv = 1.f / fmaxf(mn, 1e-8f);
            float dot = 0.f;
            #pragma unroll
            for (int kk = 0; kk < NC; kk++) {
                s_cmn2[(tid - 1) * NC + kk] = m[kk] * inv;
                dot += m[kk] * s_red[tid * PCX + NC + kk];
            }
            intra_c = (double)dot / ((double)fmaxf(mn, 1e-30f) * (double)cf);
        }
    }
    __syncthreads();
    double intra = blockReduceD(intra_c);
    __syncthreads();

    double acc = 0.0;
    for (int p = tid; p < 1225; p += BLK1) {
        int i = 0, rem = p;
        while (rem >= (NL - 2) - i) { rem -= (NL - 2) - i; i++; }
        int jx = i + 1 + rem;
        float d = 0.f;
        #pragma unroll
        for (int kk = 0; kk < NC; kk++) d += s_cmn2[i * NC + kk] * s_cmn2[jx * NC + kk];
        d = fminf(fmaxf(d, 0.f), 1.f);
        acc += (double)d;
    }
    __syncthreads();
    double inter = blockReduceD(acc);
    if (tid == 0) out[0] = (float)(inter / 1225.0 - intra / (double)(NL - 1));
}

extern "C" void kernel_launch(void* const* d_in, const int* in_sizes, int n_in,
                              void* d_out, int out_size) {
    const float* pred = (const float*)d_in[0];
    const int* gt = (const int*)d_in[1];
    float* out = (float*)d_out;

    cudaFuncSetAttribute(k_fused, cudaFuncAttributeMaxDynamicSharedMemorySize, SMEM1);
    k_fused<<<GRID1, BLK1, SMEM1>>>(pred, gt, out);
}